// round 1
// baseline (speedup 1.0000x reference)
#include <cuda_runtime.h>
#include <math.h>

#define NN 100000
#define EE 1600000
#define ET (EE + NN)
#define NB_SCAN ((NN + 1023) / 1024)   // 98

// ---------------- scratch (static device globals; no allocation) ----------------
__device__ int   g_deg[NN];
__device__ int   g_fill[NN];
__device__ int   g_rowptr[NN + 1];
__device__ int   g_csrsrc[ET];
__device__ int   g_bsum[128];
__device__ int   g_total;
__device__ float g_h1[NN * 128];
__device__ float g_as1[NN * 8];
__device__ float g_ad1[NN * 8];
__device__ float g_act1[NN * 128];
__device__ float g_h2[NN * 16];
__device__ float g_as2[NN];
__device__ float g_ad2[NN];

// ---------------- CSR build ----------------
__global__ void zero_k() {
    int i = blockIdx.x * blockDim.x + threadIdx.x;
    if (i < NN) { g_deg[i] = 0; g_fill[i] = 0; }
}

__global__ void hist_k(const int* __restrict__ ei) {
    int i = blockIdx.x * blockDim.x + threadIdx.x;
    if (i >= ET) return;
    int t = (i < EE) ? ei[EE + i] : (i - EE);   // self-loop tail
    atomicAdd(&g_deg[t], 1);
}

__global__ void scan1_k() {
    __shared__ int sh[1024];
    int t = threadIdx.x;
    int i = blockIdx.x * 1024 + t;
    int v = (i < NN) ? g_deg[i] : 0;
    sh[t] = v;
    __syncthreads();
    for (int off = 1; off < 1024; off <<= 1) {
        int add = (t >= off) ? sh[t - off] : 0;
        __syncthreads();
        sh[t] += add;
        __syncthreads();
    }
    if (i < NN) g_rowptr[i] = sh[t] - v;        // exclusive within block
    if (t == 1023) g_bsum[blockIdx.x] = sh[1023];
}

__global__ void scan2_k() {
    __shared__ int sh[128];
    int t = threadIdx.x;
    int v = (t < NB_SCAN) ? g_bsum[t] : 0;
    sh[t] = v;
    __syncthreads();
    for (int off = 1; off < 128; off <<= 1) {
        int add = (t >= off) ? sh[t - off] : 0;
        __syncthreads();
        sh[t] += add;
        __syncthreads();
    }
    if (t < NB_SCAN) g_bsum[t] = sh[t] - v;     // exclusive block offsets
    if (t == 127) g_total = sh[127];
}

__global__ void scan3_k() {
    int i = blockIdx.x * 1024 + threadIdx.x;
    if (i < NN) g_rowptr[i] += g_bsum[blockIdx.x];
    if (i == 0) g_rowptr[NN] = g_total;
}

__global__ void scatter_k(const int* __restrict__ ei) {
    int i = blockIdx.x * blockDim.x + threadIdx.x;
    if (i >= ET) return;
    int s, t;
    if (i < EE) { s = ei[i]; t = ei[EE + i]; }
    else        { s = i - EE; t = i - EE; }
    int pos = atomicAdd(&g_fill[t], 1);
    g_csrsrc[g_rowptr[t] + pos] = s;
}

// ---------------- layer 1 GEMM: h1 = x @ W1  (128x128) ----------------
__global__ void gemm1_k(const float* __restrict__ X, const float* __restrict__ W) {
    __shared__ float xs[64][32];    // [row][k]
    __shared__ float ws[32][128];   // [k][col]
    int tid = threadIdx.x;          // 256
    int tx = tid & 31;              // col group: c0 = tx*4
    int ty = tid >> 5;              // row group: r0 = ty*8
    int rowBase = blockIdx.x * 64;

    float acc[8][4];
#pragma unroll
    for (int i = 0; i < 8; i++)
#pragma unroll
        for (int j = 0; j < 4; j++) acc[i][j] = 0.f;

    for (int kb = 0; kb < 128; kb += 32) {
#pragma unroll
        for (int j = 0; j < 8; j++) {
            int e = j * 256 + tid;
            int r = e >> 5, k = e & 31;
            int gr = rowBase + r;
            xs[r][k] = (gr < NN) ? X[gr * 128 + kb + k] : 0.f;
        }
#pragma unroll
        for (int j = 0; j < 16; j++) {
            int e = j * 256 + tid;
            int k = e >> 7, c = e & 127;
            ws[k][c] = W[(kb + k) * 128 + c];
        }
        __syncthreads();
#pragma unroll
        for (int k = 0; k < 32; k++) {
            float4 wv = *(const float4*)&ws[k][tx * 4];
            float xr[8];
#pragma unroll
            for (int i = 0; i < 8; i++) xr[i] = xs[ty * 8 + i][k];
#pragma unroll
            for (int i = 0; i < 8; i++) {
                acc[i][0] += xr[i] * wv.x;
                acc[i][1] += xr[i] * wv.y;
                acc[i][2] += xr[i] * wv.z;
                acc[i][3] += xr[i] * wv.w;
            }
        }
        __syncthreads();
    }
#pragma unroll
    for (int i = 0; i < 8; i++) {
        int gr = rowBase + ty * 8 + i;
        if (gr < NN)
            *(float4*)&g_h1[gr * 128 + tx * 4] =
                make_float4(acc[i][0], acc[i][1], acc[i][2], acc[i][3]);
    }
}

// ---------------- layer 1 attention coefficients ----------------
__global__ void alpha1_k(const float* __restrict__ Asrc, const float* __restrict__ Adst) {
    int idx = blockIdx.x * blockDim.x + threadIdx.x;
    if (idx >= NN * 8) return;
    int n = idx >> 3, h = idx & 7;
    const float4* hp  = (const float4*)&g_h1[n * 128 + h * 16];
    const float4* sp  = (const float4*)&Asrc[h * 16];
    const float4* dp  = (const float4*)&Adst[h * 16];
    float s = 0.f, d = 0.f;
#pragma unroll
    for (int j = 0; j < 4; j++) {
        float4 hv = hp[j], sa = sp[j], da = dp[j];
        s += hv.x * sa.x + hv.y * sa.y + hv.z * sa.z + hv.w * sa.w;
        d += hv.x * da.x + hv.y * da.y + hv.z * da.z + hv.w * da.w;
    }
    g_as1[idx] = s;
    g_ad1[idx] = d;
}

// ---------------- layer 1 aggregation: warp per target node ----------------
__global__ void agg1_k(const float* __restrict__ b1) {
    int warp = (blockIdx.x * blockDim.x + threadIdx.x) >> 5;
    int lane = threadIdx.x & 31;
    if (warp >= NN) return;
    int t = warp;
    int beg = g_rowptr[t], end = g_rowptr[t + 1];

    // pass 1: per-head max   (lane layout: head = lane&7, edge-slot = lane>>3)
    int hp = lane & 7;
    float adv = g_ad1[t * 8 + hp];
    float m = -1e30f;
    for (int base = beg; base < end; base += 4) {
        int idx = base + (lane >> 3);
        float e = -1e30f;
        if (idx < end) {
            int s = g_csrsrc[idx];
            float v = g_as1[s * 8 + hp] + adv;
            e = v > 0.f ? v : 0.2f * v;
        }
        m = fmaxf(m, e);
    }
    m = fmaxf(m, __shfl_xor_sync(0xffffffffu, m, 8));
    m = fmaxf(m, __shfl_xor_sync(0xffffffffu, m, 16));
    // lane h (0..7) now holds max for head h (replicated at h+8/16/24)

    // pass 2: exp-sum + weighted accumulate (lane covers channels lane*4..lane*4+3, head = lane>>2)
    int hd = lane >> 2;
    float m2  = __shfl_sync(0xffffffffu, m,   hd);
    float adh = __shfl_sync(0xffffffffu, adv, hd);
    float4 acc = make_float4(0.f, 0.f, 0.f, 0.f);
    float sumw = 0.f;
    int sN = g_csrsrc[beg];
    for (int idx = beg; idx < end; idx++) {
        int s = sN;
        if (idx + 1 < end) sN = g_csrsrc[idx + 1];
        float v = g_as1[s * 8 + hd] + adh;
        v = v > 0.f ? v : 0.2f * v;
        float w = __expf(v - m2);
        sumw += w;
        float4 hv = *(const float4*)&g_h1[s * 128 + lane * 4];
        acc.x += w * hv.x;
        acc.y += w * hv.y;
        acc.z += w * hv.z;
        acc.w += w * hv.w;
    }
    float inv = 1.f / (sumw + 1e-16f);
    int c0 = lane * 4;
    float o0 = acc.x * inv + b1[c0 + 0];
    float o1 = acc.y * inv + b1[c0 + 1];
    float o2 = acc.z * inv + b1[c0 + 2];
    float o3 = acc.w * inv + b1[c0 + 3];
    // ELU
    o0 = o0 > 0.f ? o0 : __expf(o0) - 1.f;
    o1 = o1 > 0.f ? o1 : __expf(o1) - 1.f;
    o2 = o2 > 0.f ? o2 : __expf(o2) - 1.f;
    o3 = o3 > 0.f ? o3 : __expf(o3) - 1.f;
    *(float4*)&g_act1[t * 128 + c0] = make_float4(o0, o1, o2, o3);
}

// ---------------- layer 2 GEMM (128 -> 16) + attention coefficients, fused ----------------
__global__ void gemm2_k(const float* __restrict__ W2,
                        const float* __restrict__ Asrc, const float* __restrict__ Adst) {
    __shared__ float w2s[128 * 16];
    int t = threadIdx.x;   // 128
#pragma unroll
    for (int j = 0; j < 16; j++) w2s[j * 128 + t] = W2[j * 128 + t];
    __syncthreads();
    int n = blockIdx.x * 128 + t;
    if (n >= NN) return;

    float acc[16];
#pragma unroll
    for (int c = 0; c < 16; c++) acc[c] = 0.f;

    const float4* xp = (const float4*)&g_act1[n * 128];
#pragma unroll 4
    for (int k4 = 0; k4 < 32; k4++) {
        float4 xv = xp[k4];
#pragma unroll
        for (int j = 0; j < 4; j++) {
            int k = k4 * 4 + j;
            float xk = (j == 0) ? xv.x : (j == 1) ? xv.y : (j == 2) ? xv.z : xv.w;
            const float4* wr = (const float4*)&w2s[k * 16];
            float4 w0 = wr[0], w1 = wr[1], w2v = wr[2], w3 = wr[3];
            acc[0]  += xk * w0.x;  acc[1]  += xk * w0.y;  acc[2]  += xk * w0.z;  acc[3]  += xk * w0.w;
            acc[4]  += xk * w1.x;  acc[5]  += xk * w1.y;  acc[6]  += xk * w1.z;  acc[7]  += xk * w1.w;
            acc[8]  += xk * w2v.x; acc[9]  += xk * w2v.y; acc[10] += xk * w2v.z; acc[11] += xk * w2v.w;
            acc[12] += xk * w3.x;  acc[13] += xk * w3.y;  acc[14] += xk * w3.z;  acc[15] += xk * w3.w;
        }
    }
    float s = 0.f, d = 0.f;
#pragma unroll
    for (int c = 0; c < 16; c++) { s += acc[c] * Asrc[c]; d += acc[c] * Adst[c]; }
    float4* hp = (float4*)&g_h2[n * 16];
    hp[0] = make_float4(acc[0],  acc[1],  acc[2],  acc[3]);
    hp[1] = make_float4(acc[4],  acc[5],  acc[6],  acc[7]);
    hp[2] = make_float4(acc[8],  acc[9],  acc[10], acc[11]);
    hp[3] = make_float4(acc[12], acc[13], acc[14], acc[15]);
    g_as2[n] = s;
    g_ad2[n] = d;
}

// ---------------- layer 2 aggregation: warp per target node ----------------
__global__ void agg2_k(const float* __restrict__ b2, float* __restrict__ out) {
    int warp = (blockIdx.x * blockDim.x + threadIdx.x) >> 5;
    int lane = threadIdx.x & 31;
    if (warp >= NN) return;
    int t = warp;
    int beg = g_rowptr[t], end = g_rowptr[t + 1];
    float adv = g_ad2[t];

    // pass 1: max over incoming edges
    float m = -1e30f;
    for (int base = beg; base < end; base += 32) {
        int idx = base + lane;
        float e = -1e30f;
        if (idx < end) {
            int s = g_csrsrc[idx];
            float v = g_as2[s] + adv;
            e = v > 0.f ? v : 0.2f * v;
        }
        m = fmaxf(m, e);
    }
#pragma unroll
    for (int o = 16; o > 0; o >>= 1) m = fmaxf(m, __shfl_xor_sync(0xffffffffu, m, o));

    // pass 2: two edges per iteration; lane covers channel lane&15, half = lane>>4
    int c = lane & 15;
    float acc = 0.f, sumw = 0.f;
    for (int base = beg; base < end; base += 2) {
        int idx = base + (lane >> 4);
        if (idx < end) {
            int s = g_csrsrc[idx];
            float v = g_as2[s] + adv;
            v = v > 0.f ? v : 0.2f * v;
            float w = __expf(v - m);
            sumw += w;
            acc += w * g_h2[s * 16 + c];
        }
    }
    sumw += __shfl_xor_sync(0xffffffffu, sumw, 16);
    acc  += __shfl_xor_sync(0xffffffffu, acc, 16);
    if (lane < 16) out[t * 16 + c] = acc / (sumw + 1e-16f) + b2[c];
}

// ---------------- launch ----------------
extern "C" void kernel_launch(void* const* d_in, const int* in_sizes, int n_in,
                              void* d_out, int out_size) {
    const float* x    = (const float*)d_in[0];
    const int*   ei   = (const int*)  d_in[1];
    const float* W1   = (const float*)d_in[2];
    const float* as1  = (const float*)d_in[3];
    const float* ad1  = (const float*)d_in[4];
    const float* b1   = (const float*)d_in[5];
    const float* W2   = (const float*)d_in[6];
    const float* as2  = (const float*)d_in[7];
    const float* ad2  = (const float*)d_in[8];
    const float* b2   = (const float*)d_in[9];
    float* out = (float*)d_out;

    // CSR build (shared by both layers)
    zero_k   <<<(NN + 255) / 256, 256>>>();
    hist_k   <<<(ET + 255) / 256, 256>>>(ei);
    scan1_k  <<<NB_SCAN, 1024>>>();
    scan2_k  <<<1, 128>>>();
    scan3_k  <<<NB_SCAN, 1024>>>();
    scatter_k<<<(ET + 255) / 256, 256>>>(ei);

    // layer 1
    gemm1_k  <<<(NN + 63) / 64, 256>>>(x, W1);
    alpha1_k <<<(NN * 8 + 255) / 256, 256>>>(as1, ad1);
    agg1_k   <<<(NN + 7) / 8, 256>>>(b1);

    // layer 2
    gemm2_k  <<<(NN + 127) / 128, 128>>>(W2, as2, ad2);
    agg2_k   <<<(NN + 7) / 8, 256>>>(b2, out);
}